// round 16
// baseline (speedup 1.0000x reference)
#include <cuda_runtime.h>
#include <cuda_bf16.h>
#include <math.h>
#include <stdint.h>

// ---------------------------------------------------------------------------
// Fixed problem shape
// ---------------------------------------------------------------------------
#define D_MODEL 1024
#define HEADS   16
#define HEAD_DIM 64
#define FF_DIM  4096
#define SEQ_L   2048
#define EPS     1e-5f
#define MROWS   4096      // B * L

// ---------------------------------------------------------------------------
// Scratch (static device globals; no runtime allocation allowed)
// ---------------------------------------------------------------------------
__device__ float g_proj[MROWS * D_MODEL];
__device__ float g_h   [MROWS * D_MODEL];
__device__ float g_tmp [MROWS * D_MODEL];
__device__ float g_bqkv[3 * D_MODEL];

// split activations (bf16 hi/lo)
__device__ __nv_bfloat16 g_xh[MROWS * D_MODEL];
__device__ __nv_bfloat16 g_xl[MROWS * D_MODEL];
__device__ __nv_bfloat16 g_qh[MROWS * D_MODEL];
__device__ __nv_bfloat16 g_ql[MROWS * D_MODEL];
__device__ __nv_bfloat16 g_kh[MROWS * D_MODEL];
__device__ __nv_bfloat16 g_kl[MROWS * D_MODEL];
__device__ __nv_bfloat16 g_vh[MROWS * D_MODEL];
__device__ __nv_bfloat16 g_vl[MROWS * D_MODEL];
__device__ __nv_bfloat16 g_ah[MROWS * D_MODEL];
__device__ __nv_bfloat16 g_al[MROWS * D_MODEL];
__device__ __nv_bfloat16 g_hh[MROWS * D_MODEL];
__device__ __nv_bfloat16 g_hl[MROWS * D_MODEL];
__device__ __nv_bfloat16 g_ffh[MROWS * FF_DIM];
__device__ __nv_bfloat16 g_ffl[MROWS * FF_DIM];

// weights: QKV concatenated [3072][1024]; Wm; W1; W2 (all [N][K] bf16 hi/lo)
__device__ __nv_bfloat16 g_wqkv_h[3 * D_MODEL * D_MODEL];
__device__ __nv_bfloat16 g_wqkv_l[3 * D_MODEL * D_MODEL];
__device__ __nv_bfloat16 g_wm_h[D_MODEL * D_MODEL];
__device__ __nv_bfloat16 g_wm_l[D_MODEL * D_MODEL];
__device__ __nv_bfloat16 g_w1_h[D_MODEL * FF_DIM];
__device__ __nv_bfloat16 g_w1_l[D_MODEL * FF_DIM];
__device__ __nv_bfloat16 g_w2_h[FF_DIM * D_MODEL];
__device__ __nv_bfloat16 g_w2_l[FF_DIM * D_MODEL];

// ---------------------------------------------------------------------------
// Helpers (base sm_100-safe: ldmatrix + mma.sync + cp.async)
// ---------------------------------------------------------------------------
__device__ __forceinline__ uint32_t smem_u32(const void* p) {
    uint32_t a;
    asm("{ .reg .u64 t; cvta.to.shared.u64 t, %1; cvt.u32.u64 %0, t; }" : "=r"(a) : "l"(p));
    return a;
}
__device__ __forceinline__ void ldsm4(uint32_t* r, uint32_t addr) {
    asm volatile("ldmatrix.sync.aligned.m8n8.x4.shared.b16 {%0,%1,%2,%3}, [%4];"
                 : "=r"(r[0]), "=r"(r[1]), "=r"(r[2]), "=r"(r[3]) : "r"(addr));
}
__device__ __forceinline__ void ldsm4t(uint32_t* r, uint32_t addr) {
    asm volatile("ldmatrix.sync.aligned.m8n8.x4.trans.shared.b16 {%0,%1,%2,%3}, [%4];"
                 : "=r"(r[0]), "=r"(r[1]), "=r"(r[2]), "=r"(r[3]) : "r"(addr));
}
__device__ __forceinline__ void mma16816(float* d, const uint32_t* a, const uint32_t* b) {
    asm volatile("mma.sync.aligned.m16n8k16.row.col.f32.bf16.bf16.f32 "
                 "{%0,%1,%2,%3}, {%4,%5,%6,%7}, {%8,%9}, {%0,%1,%2,%3};"
                 : "+f"(d[0]), "+f"(d[1]), "+f"(d[2]), "+f"(d[3])
                 : "r"(a[0]), "r"(a[1]), "r"(a[2]), "r"(a[3]), "r"(b[0]), "r"(b[1]));
}
__device__ __forceinline__ void cp_async16(uint32_t saddr, const void* gptr) {
    asm volatile("cp.async.cg.shared.global [%0], [%1], 16;"
                 :: "r"(saddr), "l"(gptr) : "memory");
}
__device__ __forceinline__ void cp_commit() {
    asm volatile("cp.async.commit_group;" ::: "memory");
}
template<int N> __device__ __forceinline__ void cp_wait() {
    asm volatile("cp.async.wait_group %0;" :: "n"(N) : "memory");
}
__device__ __forceinline__ uint32_t packbf(float a, float b) {
    __nv_bfloat162 t = __float22bfloat162_rn(make_float2(a, b));
    return *reinterpret_cast<uint32_t*>(&t);
}
__device__ __forceinline__ float2 unpackbf(uint32_t u) {
    return __bfloat1622float2(*reinterpret_cast<__nv_bfloat162*>(&u));
}

// ---------------------------------------------------------------------------
// Weight transpose + hi/lo split: W[K,N] fp32 -> Th/Tl[N,K] bf16
// ---------------------------------------------------------------------------
__global__ __launch_bounds__(256) void transpose_split_kernel(
    const float* __restrict__ W, __nv_bfloat16* __restrict__ Th,
    __nv_bfloat16* __restrict__ Tl, int K, int N)
{
    __shared__ float t[32][33];
    const int n0 = blockIdx.x * 32, k0 = blockIdx.y * 32;
    const int tx = threadIdx.x & 31, ty = threadIdx.x >> 5;
#pragma unroll
    for (int i = 0; i < 4; i++)
        t[ty + i * 8][tx] = W[(size_t)(k0 + ty + i * 8) * N + n0 + tx];
    __syncthreads();
#pragma unroll
    for (int i = 0; i < 4; i++) {
        float v = t[tx][ty + i * 8];
        __nv_bfloat16 h = __float2bfloat16(v);
        __nv_bfloat16 l = __float2bfloat16(v - __bfloat162float(h));
        size_t o = (size_t)(n0 + ty + i * 8) * K + k0 + tx;
        Th[o] = h;
        Tl[o] = l;
    }
}

// 3 square DxD transposes in one launch (grid.z selects matrix) — QKV weights
struct TS3 {
    const float* W[3];
    __nv_bfloat16* Th[3];
    __nv_bfloat16* Tl[3];
};
__global__ __launch_bounds__(256) void transpose_split3_kernel(TS3 a)
{
    __shared__ float t[32][33];
    const int m = blockIdx.z;
    const float* W = a.W[m];
    __nv_bfloat16* Th = a.Th[m];
    __nv_bfloat16* Tl = a.Tl[m];
    const int n0 = blockIdx.x * 32, k0 = blockIdx.y * 32;
    const int tx = threadIdx.x & 31, ty = threadIdx.x >> 5;
#pragma unroll
    for (int i = 0; i < 4; i++)
        t[ty + i * 8][tx] = W[(size_t)(k0 + ty + i * 8) * D_MODEL + n0 + tx];
    __syncthreads();
#pragma unroll
    for (int i = 0; i < 4; i++) {
        float v = t[tx][ty + i * 8];
        __nv_bfloat16 h = __float2bfloat16(v);
        __nv_bfloat16 l = __float2bfloat16(v - __bfloat162float(h));
        size_t o = (size_t)(n0 + ty + i * 8) * D_MODEL + k0 + tx;
        Th[o] = h;
        Tl[o] = l;
    }
}

// ---------------------------------------------------------------------------
// Elementwise hi/lo split: x fp32 -> xh, xl bf16
// ---------------------------------------------------------------------------
__global__ __launch_bounds__(256) void split_kernel(
    const float* __restrict__ x, __nv_bfloat16* __restrict__ xh,
    __nv_bfloat16* __restrict__ xl, int n4)
{
    int i = blockIdx.x * 256 + threadIdx.x;
    if (i >= n4) return;
    float4 v = *(const float4*)(x + (size_t)i * 4);
    uint32_t h0 = packbf(v.x, v.y), h1 = packbf(v.z, v.w);
    float2 f0 = unpackbf(h0), f1 = unpackbf(h1);
    uint32_t l0 = packbf(v.x - f0.x, v.y - f0.y);
    uint32_t l1 = packbf(v.z - f1.x, v.w - f1.y);
    *(uint2*)((char*)xh + (size_t)i * 8) = make_uint2(h0, h1);
    *(uint2*)((char*)xl + (size_t)i * 8) = make_uint2(l0, l1);
}

// ---------------------------------------------------------------------------
// HMMA GEMM, 3-stage cp.async pipeline, 2 CTAs/SM (128-reg cap).
// If Ch1 != null: fused-QKV mode (N spans 3 concatenated outputs).
// ---------------------------------------------------------------------------
#define TBK 32
#define STAGE_BYTES 32768
#define NSTAGE 3
#define GEMM_SMEM_BYTES (NSTAGE * STAGE_BYTES)   // 96KB/CTA; 2 CTAs = 192KB/SM

__global__ __launch_bounds__(256, 2)
void gemm_tc_kernel(const __nv_bfloat16* __restrict__ Ah,
                    const __nv_bfloat16* __restrict__ Al,
                    const __nv_bfloat16* __restrict__ BTh,
                    const __nv_bfloat16* __restrict__ BTl,
                    const float* __restrict__ bias,
                    float* __restrict__ Cf,
                    __nv_bfloat16* __restrict__ Ch,
                    __nv_bfloat16* __restrict__ Cl,
                    __nv_bfloat16* __restrict__ Ch1,
                    __nv_bfloat16* __restrict__ Cl1,
                    __nv_bfloat16* __restrict__ Ch2,
                    __nv_bfloat16* __restrict__ Cl2,
                    int M, int N, int K, int relu)
{
    extern __shared__ char smem[];
    const uint32_t sb = smem_u32(smem);

    const int tid = threadIdx.x;
    const int wid = tid >> 5;
    const int lane = tid & 31;
    const int row0 = blockIdx.y * 128;
    const int col0 = blockIdx.x * 128;
    const int wm0 = (wid & 3) * 32;
    const int wn0 = (wid >> 2) * 64;
    const int nkb = K / TBK;

    const int sr = tid >> 3;
    const int sj = tid & 7;
    const __nv_bfloat16* Asrc = (sj < 4) ? Ah : Al;
    const __nv_bfloat16* Bsrc = (sj < 4) ? BTh : BTl;
    const int sk = (sj & 3) * 8;

    const int lr = lane & 7;
    const int mh = (lane >> 3) & 1;
    const int kh = (lane >> 4) & 1;
    uint32_t aRow[2], bN[4];
#pragma unroll
    for (int mt = 0; mt < 2; mt++) aRow[mt] = wm0 + mt * 16 + mh * 8 + lr;
#pragma unroll
    for (int g = 0; g < 4; g++)    bN[g]   = wn0 + g * 16 + kh * 8 + lr;

    float acc[2][8][4];
#pragma unroll
    for (int mt = 0; mt < 2; mt++)
#pragma unroll
        for (int nt = 0; nt < 8; nt++)
#pragma unroll
            for (int i = 0; i < 4; i++) acc[mt][nt][i] = 0.f;

    auto issue = [&](int kb) {
        const int s = kb % NSTAGE;
        const uint32_t Ab = sb + s * STAGE_BYTES;
        const uint32_t Bb = Ab + 16384;
#pragma unroll
        for (int it = 0; it < 4; it++) {
            const int r = sr + it * 32;
            const uint32_t off = r * 128 + ((sj ^ (r & 7)) << 4);
            cp_async16(Ab + off, Asrc + (size_t)(row0 + r) * K + kb * TBK + sk);
            cp_async16(Bb + off, Bsrc + (size_t)(col0 + r) * K + kb * TBK + sk);
        }
    };
    auto compute = [&](int s) {
        const uint32_t Ab = sb + s * STAGE_BYTES;
        const uint32_t Bb = Ab + 16384;
#pragma unroll
        for (int kc = 0; kc < 2; kc++) {
            uint32_t ah[2][4], al[2][4];
#pragma unroll
            for (int mt = 0; mt < 2; mt++) {
                const uint32_t ra = Ab + aRow[mt] * 128;
                const int sw = aRow[mt] & 7;
                ldsm4(ah[mt], ra + (((kc * 2 + kh    ) ^ sw) << 4));
                ldsm4(al[mt], ra + (((kc * 2 + kh + 4) ^ sw) << 4));
            }
#pragma unroll
            for (int g = 0; g < 4; g++) {
                const uint32_t rb = Bb + bN[g] * 128;
                const int sw = bN[g] & 7;
                uint32_t bh[4], bl[4];
                ldsm4(bh, rb + (((kc * 2 + mh    ) ^ sw) << 4));
                ldsm4(bl, rb + (((kc * 2 + mh + 4) ^ sw) << 4));
                mma16816(acc[0][2 * g],     ah[0], bh);
                mma16816(acc[1][2 * g],     ah[1], bh);
                mma16816(acc[0][2 * g + 1], ah[0], bh + 2);
                mma16816(acc[1][2 * g + 1], ah[1], bh + 2);
                mma16816(acc[0][2 * g],     ah[0], bl);
                mma16816(acc[1][2 * g],     ah[1], bl);
                mma16816(acc[0][2 * g + 1], ah[0], bl + 2);
                mma16816(acc[1][2 * g + 1], ah[1], bl + 2);
                mma16816(acc[0][2 * g],     al[0], bh);
                mma16816(acc[1][2 * g],     al[1], bh);
                mma16816(acc[0][2 * g + 1], al[0], bh + 2);
                mma16816(acc[1][2 * g + 1], al[1], bh + 2);
            }
        }
    };

    issue(0); cp_commit();
    issue(1); cp_commit();
    for (int kb = 0; kb < nkb; kb++) {
        if (kb + 1 < nkb) cp_wait<1>(); else cp_wait<0>();
        __syncthreads();
        if (kb + 2 < nkb) { issue(kb + 2); cp_commit(); }
        compute(kb % NSTAGE);
    }

    // epilogue (QKV mode: select output by column block)
    __nv_bfloat16* po_h = Ch;
    __nv_bfloat16* po_l = Cl;
    int outN = N;
    int ocol0 = col0;
    if (Ch1) {
        const int which = col0 >> 10;
        po_h = (which == 0) ? Ch : ((which == 1) ? Ch1 : Ch2);
        po_l = (which == 0) ? Cl : ((which == 1) ? Cl1 : Cl2);
        outN = D_MODEL;
        ocol0 = col0 - (which << 10);
    }
    const int qr = lane >> 2;
    const int qc = (lane & 3) * 2;
#pragma unroll
    for (int mt = 0; mt < 2; mt++) {
#pragma unroll
        for (int nt = 0; nt < 8; nt++) {
            const int r = row0 + wm0 + mt * 16 + qr;
            const int cg = col0 + wn0 + nt * 8 + qc;     // bias index
            const int c  = ocol0 + wn0 + nt * 8 + qc;    // output col
            const float b0 = bias[cg], b1 = bias[cg + 1];
            float v0 = acc[mt][nt][0] + b0;
            float v1 = acc[mt][nt][1] + b1;
            float v2 = acc[mt][nt][2] + b0;
            float v3 = acc[mt][nt][3] + b1;
            if (relu) {
                v0 = fmaxf(v0, 0.f); v1 = fmaxf(v1, 0.f);
                v2 = fmaxf(v2, 0.f); v3 = fmaxf(v3, 0.f);
            }
            if (Cf) {
                *(float2*)(Cf + (size_t)r * N + c) = make_float2(v0, v1);
                *(float2*)(Cf + (size_t)(r + 8) * N + c) = make_float2(v2, v3);
            }
            if (po_h) {
                uint32_t h0 = packbf(v0, v1);
                uint32_t h1 = packbf(v2, v3);
                float2 f0 = unpackbf(h0), f1 = unpackbf(h1);
                uint32_t l0 = packbf(v0 - f0.x, v1 - f0.y);
                uint32_t l1 = packbf(v2 - f1.x, v3 - f1.y);
                *(uint32_t*)((char*)po_h + ((size_t)r * outN + c) * 2) = h0;
                *(uint32_t*)((char*)po_h + ((size_t)(r + 8) * outN + c) * 2) = h1;
                *(uint32_t*)((char*)po_l + ((size_t)r * outN + c) * 2) = l0;
                *(uint32_t*)((char*)po_l + ((size_t)(r + 8) * outN + c) * 2) = l1;
            }
        }
    }
}

// ---------------------------------------------------------------------------
// Flash-attention with HMMA (split-3 bf16, fp32 accum), cp.async staging.
// 2 CTAs/SM. grid.y = HEADS (single batch per launch, pointers pre-offset).
// ---------------------------------------------------------------------------
#define ATTN_SMEM 98304

__global__ __launch_bounds__(256, 2)
void attn_tc_kernel(const __nv_bfloat16* __restrict__ qh, const __nv_bfloat16* __restrict__ ql,
                    const __nv_bfloat16* __restrict__ kh_g, const __nv_bfloat16* __restrict__ kl_g,
                    const __nv_bfloat16* __restrict__ vh_g, const __nv_bfloat16* __restrict__ vl_g,
                    __nv_bfloat16* __restrict__ oh, __nv_bfloat16* __restrict__ ol, int L)
{
    extern __shared__ char smem[];
    const uint32_t sb = smem_u32(smem);
    const uint32_t qoff = sb;
    const uint32_t koff = sb + 32768;
    const uint32_t voff = sb + 65536;

    const int tid = threadIdx.x;
    const int wid = tid >> 5;
    const int lane = tid & 31;
    const int bh_ = blockIdx.y;
    const int b = bh_ / HEADS;
    const int hd = (bh_ % HEADS) * HEAD_DIM;
    const int l0 = blockIdx.x * 128;
    const int tok0 = b * L + l0;
    const int kbase = b * L;

    const int lr = lane & 7;
    const int mh = (lane >> 3) & 1;
    const int khb = (lane >> 4) & 1;

    auto issueKV = [&](int kb) {
        const int t0 = kbase + kb * 64;
        const int s = kb & 1;
        const uint32_t kb_ = koff + s * 16384;
        const uint32_t vb_ = voff + s * 16384;
#pragma unroll
        for (int it = 0; it < 4; it++) {
            int id = it * 256 + tid;
            {
                int c = id >> 9, row = (id >> 3) & 63, j = id & 7;
                const __nv_bfloat16* src = (j < 4) ? kh_g : kl_g;
                cp_async16(kb_ + c * 8192 + row * 128 + ((j ^ (row & 7)) << 4),
                           src + (size_t)(t0 + row) * D_MODEL + hd + c * 32 + (j & 3) * 8);
            }
            {
                int row = (id >> 3) & 63, j = id & 7;
                const __nv_bfloat16* src = (id < 512) ? vh_g : vl_g;
                cp_async16(vb_ + ((id < 512) ? 0 : 8192) + row * 128 + ((j ^ (row & 7)) << 4),
                           src + (size_t)(t0 + row) * D_MODEL + hd + j * 8);
            }
        }
    };

#pragma unroll
    for (int it = 0; it < 8; it++) {
        int id = it * 256 + tid;
        int c = id >> 10, rem = id & 1023;
        int row = rem >> 3, j = rem & 7;
        const __nv_bfloat16* src = (j < 4) ? qh : ql;
        cp_async16(qoff + c * 16384 + row * 128 + ((j ^ (row & 7)) << 4),
                   src + (size_t)(tok0 + row) * D_MODEL + hd + c * 32 + (j & 3) * 8);
    }
    cp_commit();
    issueKV(0); cp_commit();
    cp_wait<0>();
    __syncthreads();

    const int aRow = wid * 16 + mh * 8 + lr;
    const int asw = aRow & 7;

    float m0 = -3.0e38f, m1 = -3.0e38f, li0 = 0.f, li1 = 0.f;
    float oacc[8][4];
#pragma unroll
    for (int j = 0; j < 8; j++)
#pragma unroll
        for (int i = 0; i < 4; i++) oacc[j][i] = 0.f;

    const int nkb = L / 64;
    for (int kb = 0; kb < nkb; kb++) {
        const int s = kb & 1;
        if (kb) {
            cp_wait<0>();
            __syncthreads();
        }
        if (kb + 1 < nkb) { issueKV(kb + 1); cp_commit(); }

        // ---- S = Q @ K^T ----
        float sacc[8][4];
#pragma unroll
        for (int j = 0; j < 8; j++)
#pragma unroll
            for (int i = 0; i < 4; i++) sacc[j][i] = 0.f;

        const uint32_t kst = koff + s * 16384;
#pragma unroll
        for (int c = 0; c < 2; c++) {
            const uint32_t qbase = qoff + c * 16384 + aRow * 128;
#pragma unroll
            for (int kc = 0; kc < 2; kc++) {
                uint32_t qah[4], qal[4];
                ldsm4(qah, qbase + (((kc * 2 + khb    ) ^ asw) << 4));
                ldsm4(qal, qbase + (((kc * 2 + khb + 4) ^ asw) << 4));
#pragma unroll
                for (int g = 0; g < 4; g++) {
                    const int bN = g * 16 + khb * 8 + lr;
                    const int sw = bN & 7;
                    const uint32_t rb = kst + c * 8192 + bN * 128;
                    uint32_t kbh[4], kbl[4];
                    ldsm4(kbh, rb + (((kc * 2 + mh    ) ^ sw) << 4));
                    ldsm4(kbl, rb + (((kc * 2 + mh + 4) ^ sw) << 4));
                    mma16816(sacc[2 * g],     qah, kbh);
                    mma16816(sacc[2 * g + 1], qah, kbh + 2);
                    mma16816(sacc[2 * g],     qah, kbl);
                    mma16816(sacc[2 * g + 1], qah, kbl + 2);
                    mma16816(sacc[2 * g],     qal, kbh);
                    mma16816(sacc[2 * g + 1], qal, kbh + 2);
                }
            }
        }

        // ---- online softmax ----
#pragma unroll
        for (int j = 0; j < 8; j++)
#pragma unroll
            for (int i = 0; i < 4; i++) sacc[j][i] *= 0.125f;

        float mx0 = -3.0e38f, mx1 = -3.0e38f;
#pragma unroll
        for (int j = 0; j < 8; j++) {
            mx0 = fmaxf(mx0, fmaxf(sacc[j][0], sacc[j][1]));
            mx1 = fmaxf(mx1, fmaxf(sacc[j][2], sacc[j][3]));
        }
        mx0 = fmaxf(mx0, __shfl_xor_sync(0xffffffffu, mx0, 1));
        mx0 = fmaxf(mx0, __shfl_xor_sync(0xffffffffu, mx0, 2));
        mx1 = fmaxf(mx1, __shfl_xor_sync(0xffffffffu, mx1, 1));
        mx1 = fmaxf(mx1, __shfl_xor_sync(0xffffffffu, mx1, 2));
        const float mn0 = fmaxf(m0, mx0);
        const float mn1 = fmaxf(m1, mx1);
        const float co0 = __expf(m0 - mn0);
        const float co1 = __expf(m1 - mn1);
        float rs0 = 0.f, rs1 = 0.f;
#pragma unroll
        for (int j = 0; j < 8; j++) {
            sacc[j][0] = __expf(sacc[j][0] - mn0);
            sacc[j][1] = __expf(sacc[j][1] - mn0);
            sacc[j][2] = __expf(sacc[j][2] - mn1);
            sacc[j][3] = __expf(sacc[j][3] - mn1);
            rs0 += sacc[j][0] + sacc[j][1];
            rs1 += sacc[j][2] + sacc[j][3];
        }
        rs0 += __shfl_xor_sync(0xffffffffu, rs0, 1);
        rs0 += __shfl_xor_sync(0xffffffffu, rs0, 2);
        rs1 += __shfl_xor_sync(0xffffffffu, rs1, 1);
        rs1 += __shfl_xor_sync(0xffffffffu, rs1, 2);
        li0 = li0 * co0 + rs0;
        li1 = li1 * co1 + rs1;
        m0 = mn0; m1 = mn1;
#pragma unroll
        for (int j = 0; j < 8; j++) {
            oacc[j][0] *= co0; oacc[j][1] *= co0;
            oacc[j][2] *= co1; oacc[j][3] *= co1;
        }

        // ---- O += P @ V ----
        const uint32_t vst = voff + s * 16384;
#pragma unroll
        for (int t = 0; t < 4; t++) {
            const int j0 = 2 * t, j1 = 2 * t + 1;
            uint32_t ph[4], pl[4];
            ph[0] = packbf(sacc[j0][0], sacc[j0][1]);
            ph[1] = packbf(sacc[j0][2], sacc[j0][3]);
            ph[2] = packbf(sacc[j1][0], sacc[j1][1]);
            ph[3] = packbf(sacc[j1][2], sacc[j1][3]);
#pragma unroll
            for (int i = 0; i < 4; i++) {
                float2 f = unpackbf(ph[i]);
                const float* sp = (i < 2) ? sacc[j0] : sacc[j1];
                int o = (i & 1) * 2;
                pl[i] = packbf(sp[o] - f.x, sp[o + 1] - f.y);
            }
            const int vRow = t * 16 + mh * 8 + lr;
            const int sw = vRow & 7;
            const uint32_t vrb = vst + vRow * 128;
#pragma unroll
            for (int g = 0; g < 4; g++) {
                uint32_t vvh[4], vvl[4];
                ldsm4t(vvh, vrb + (((g * 2 + khb) ^ sw) << 4));
                ldsm4t(vvl, vrb + 8192 + (((g * 2 + khb) ^ sw) << 4));
                mma16816(oacc[2 * g],     ph, vvh);
                mma16816(oacc[2 * g + 1], ph, vvh + 2);
                mma16816(oacc[2 * g],     ph, vvl);
                mma16816(oacc[2 * g + 1], ph, vvl + 2);
                mma16816(oacc[2 * g],     pl, vvh);
                mma16816(oacc[2 * g + 1], pl, vvh + 2);
            }
        }
    }

    // ---- epilogue ----
    const float inv0 = 1.f / li0;
    const float inv1 = 1.f / li1;
    const int r0 = tok0 + wid * 16 + (lane >> 2);
    const int r1 = r0 + 8;
#pragma unroll
    for (int j = 0; j < 8; j++) {
        const int c = hd + j * 8 + (lane & 3) * 2;
        float v0 = oacc[j][0] * inv0, v1 = oacc[j][1] * inv0;
        float v2 = oacc[j][2] * inv1, v3 = oacc[j][3] * inv1;
        uint32_t h0 = packbf(v0, v1), h1 = packbf(v2, v3);
        float2 f0 = unpackbf(h0), f1 = unpackbf(h1);
        uint32_t lo0 = packbf(v0 - f0.x, v1 - f0.y);
        uint32_t lo1 = packbf(v2 - f1.x, v3 - f1.y);
        *(uint32_t*)((char*)oh + ((size_t)r0 * D_MODEL + c) * 2) = h0;
        *(uint32_t*)((char*)ol + ((size_t)r0 * D_MODEL + c) * 2) = lo0;
        *(uint32_t*)((char*)oh + ((size_t)r1 * D_MODEL + c) * 2) = h1;
        *(uint32_t*)((char*)ol + ((size_t)r1 * D_MODEL + c) * 2) = lo1;
    }
}

// ---------------------------------------------------------------------------
// Fused residual + LayerNorm (+ optional split bf16 outputs)
// ---------------------------------------------------------------------------
__global__ __launch_bounds__(256) void ln_residual_kernel(
    const float* __restrict__ a, const float* __restrict__ r,
    const float* __restrict__ g, const float* __restrict__ beta,
    float* __restrict__ out, __nv_bfloat16* __restrict__ outh,
    __nv_bfloat16* __restrict__ outl)
{
    __shared__ float red[8];
    const int row = blockIdx.x;
    const int tid = threadIdx.x;
    const int lane = tid & 31, warp = tid >> 5;
    const size_t off = (size_t)row * D_MODEL + tid * 4;

    float4 va = *(const float4*)(a + off);
    float4 vr = *(const float4*)(r + off);
    float x[4] = {va.x + vr.x, va.y + vr.y, va.z + vr.z, va.w + vr.w};

    float sum = x[0] + x[1] + x[2] + x[3];
#pragma unroll
    for (int o = 16; o; o >>= 1) sum += __shfl_down_sync(0xffffffffu, sum, o);
    if (lane == 0) red[warp] = sum;
    __syncthreads();
    if (warp == 0) {
        float v = (lane < 8) ? red[lane] : 0.f;
#pragma unroll
        for (int o = 4; o; o >>= 1) v += __shfl_down_sync(0xffu, v, o);
        if (lane == 0) red[0] = v;
    }
    __syncthreads();
    const float mu = red[0] * (1.f / D_MODEL);
    __syncthreads();

    float sq = 0.f;
#pragma unroll
    for (int i = 0; i < 4; i++) {
        float d = x[i] - mu;
        sq += d * d;
    }
#pragma unroll
    for (int o = 16; o; o >>= 1) sq += __shfl_down_sync(0xffffffffu, sq, o);
    if (lane == 0) red[warp] = sq;
    __syncthreads();
    if (warp == 0) {
        float v = (lane < 8) ? red[lane] : 0.f;
#pragma unroll
        for (int o = 4; o; o >>= 1) v += __shfl_down_sync(0xffu, v, o);
        if (lane == 0) red[0] = v;
    }
    __syncthreads();
    const float rstd = rsqrtf(red[0] * (1.f / D_MODEL) + EPS);

    float4 gg = *(const float4*)(g + tid * 4);
    float4 bb = *(const float4*)(beta + tid * 4);
    float y[4];
    y[0] = (x[0] - mu) * rstd * gg.x + bb.x;
    y[1] = (x[1] - mu) * rstd * gg.y + bb.y;
    y[2] = (x[2] - mu) * rstd * gg.z + bb.z;
    y[3] = (x[3] - mu) * rstd * gg.w + bb.w;
    *(float4*)(out + off) = *(float4*)&y[0];
    if (outh) {
        uint32_t h0 = packbf(y[0], y[1]), h1 = packbf(y[2], y[3]);
        float2 f0 = unpackbf(h0), f1 = unpackbf(h1);
        uint32_t l0 = packbf(y[0] - f0.x, y[1] - f0.y);
        uint32_t l1 = packbf(y[2] - f1.x, y[3] - f1.y);
        *(uint2*)((char*)outh + off * 2) = make_uint2(h0, h1);
        *(uint2*)((char*)outl + off * 2) = make_uint2(l0, l1);
    }
}

// ---------------------------------------------------------------------------
// Launch: 4 M-chunk pipelines on the SAME 4 streams as the R12 winner
// (0, s2, s3, s4) — prep streams are reused as chunk streams after prep.
// ---------------------------------------------------------------------------
extern "C" void kernel_launch(void* const* d_in, const int* in_sizes, int n_in,
                              void* d_out, int out_size)
{
    const float* x  = (const float*)d_in[0];
    const float* Wq = (const float*)d_in[1];
    const float* bq = (const float*)d_in[2];
    const float* Wk = (const float*)d_in[3];
    const float* bk = (const float*)d_in[4];
    const float* Wv = (const float*)d_in[5];
    const float* bv = (const float*)d_in[6];
    const float* Wm = (const float*)d_in[7];
    const float* bm = (const float*)d_in[8];
    const float* W1 = (const float*)d_in[9];
    const float* b1 = (const float*)d_in[10];
    const float* W2 = (const float*)d_in[11];
    const float* b2 = (const float*)d_in[12];
    const float* g1  = (const float*)d_in[13];
    const float* be1 = (const float*)d_in[14];
    const float* g2  = (const float*)d_in[15];
    const float* be2 = (const float*)d_in[16];
    float* out = (float*)d_out;

    const int M = in_sizes[0] / D_MODEL;   // 4096
    const int L = SEQ_L;
    const int Mh = M / 2;                  // rows per batch = 2048
    const int Mq = Mh / 2;                 // rows per chunk = 1024

    float *proj, *h, *tmp, *bqkv;
    cudaGetSymbolAddress((void**)&proj, g_proj);
    cudaGetSymbolAddress((void**)&h,    g_h);
    cudaGetSymbolAddress((void**)&tmp,  g_tmp);
    cudaGetSymbolAddress((void**)&bqkv, g_bqkv);

    __nv_bfloat16 *xh, *xl, *qh, *ql, *kh, *kl, *vh, *vl, *ah, *al, *hh, *hl, *ffh, *ffl;
    cudaGetSymbolAddress((void**)&xh, g_xh); cudaGetSymbolAddress((void**)&xl, g_xl);
    cudaGetSymbolAddress((void**)&qh, g_qh); cudaGetSymbolAddress((void**)&ql, g_ql);
    cudaGetSymbolAddress((void**)&kh, g_kh); cudaGetSymbolAddress((void**)&kl, g_kl);
    cudaGetSymbolAddress((void**)&vh, g_vh); cudaGetSymbolAddress((void**)&vl, g_vl);
    cudaGetSymbolAddress((void**)&ah, g_ah); cudaGetSymbolAddress((void**)&al, g_al);
    cudaGetSymbolAddress((void**)&hh, g_hh); cudaGetSymbolAddress((void**)&hl, g_hl);
    cudaGetSymbolAddress((void**)&ffh, g_ffh); cudaGetSymbolAddress((void**)&ffl, g_ffl);

    __nv_bfloat16 *wqkvh, *wqkvl, *wmh, *wml, *w1h, *w1l, *w2h, *w2l;
    cudaGetSymbolAddress((void**)&wqkvh, g_wqkv_h); cudaGetSymbolAddress((void**)&wqkvl, g_wqkv_l);
    cudaGetSymbolAddress((void**)&wmh, g_wm_h); cudaGetSymbolAddress((void**)&wml, g_wm_l);
    cudaGetSymbolAddress((void**)&w1h, g_w1_h); cudaGetSymbolAddress((void**)&w1l, g_w1_l);
    cudaGetSymbolAddress((void**)&w2h, g_w2_h); cudaGetSymbolAddress((void**)&w2l, g_w2_l);

    static bool init_done = false;
    static cudaStream_t s2, s3, s4;
    static cudaEvent_t evFork, evJoin2, evJoin3;
    static cudaEvent_t evQ0, evQ1, evA0, evA1, evD2, evD3, evD4;
    if (!init_done) {
        cudaFuncSetAttribute(gemm_tc_kernel,
                             cudaFuncAttributeMaxDynamicSharedMemorySize, GEMM_SMEM_BYTES);
        cudaFuncSetAttribute(attn_tc_kernel,
                             cudaFuncAttributeMaxDynamicSharedMemorySize, ATTN_SMEM);
        cudaStreamCreateWithFlags(&s2, cudaStreamNonBlocking);
        cudaStreamCreateWithFlags(&s3, cudaStreamNonBlocking);
        cudaStreamCreateWithFlags(&s4, cudaStreamNonBlocking);
        cudaEventCreateWithFlags(&evFork, cudaEventDisableTiming);
        cudaEventCreateWithFlags(&evJoin2, cudaEventDisableTiming);
        cudaEventCreateWithFlags(&evJoin3, cudaEventDisableTiming);
        cudaEventCreateWithFlags(&evQ0, cudaEventDisableTiming);
        cudaEventCreateWithFlags(&evQ1, cudaEventDisableTiming);
        cudaEventCreateWithFlags(&evA0, cudaEventDisableTiming);
        cudaEventCreateWithFlags(&evA1, cudaEventDisableTiming);
        cudaEventCreateWithFlags(&evD2, cudaEventDisableTiming);
        cudaEventCreateWithFlags(&evD3, cudaEventDisableTiming);
        cudaEventCreateWithFlags(&evD4, cudaEventDisableTiming);
        init_done = true;
    }

    dim3 blk(256);

    // ---- fork ----
    cudaEventRecord(evFork, 0);
    cudaStreamWaitEvent(s2, evFork, 0);
    cudaStreamWaitEvent(s3, evFork, 0);
    cudaStreamWaitEvent(s4, evFork, 0);

    // s2: Wm / W1 / W2 transposes (needed at proj/FFN GEMMs)
    transpose_split_kernel<<<dim3(D_MODEL / 32, D_MODEL / 32), blk, 0, s2>>>(Wm, wmh, wml, D_MODEL, D_MODEL);
    transpose_split_kernel<<<dim3(FF_DIM / 32, D_MODEL / 32), blk, 0, s2>>>(W1, w1h, w1l, D_MODEL, FF_DIM);
    transpose_split_kernel<<<dim3(D_MODEL / 32, FF_DIM / 32), blk, 0, s2>>>(W2, w2h, w2l, FF_DIM, D_MODEL);
    cudaEventRecord(evJoin2, s2);

    // s3: QKV weight transposes + bias concat (needed at QKV GEMMs)
    cudaMemcpyAsync(bqkv,               bq, D_MODEL * sizeof(float), cudaMemcpyDeviceToDevice, s3);
    cudaMemcpyAsync(bqkv + D_MODEL,     bk, D_MODEL * sizeof(float), cudaMemcpyDeviceToDevice, s3);
    cudaMemcpyAsync(bqkv + 2 * D_MODEL, bv, D_MODEL * sizeof(float), cudaMemcpyDeviceToDevice, s3);
    TS3 ts;
    ts.W[0] = Wq; ts.Th[0] = wqkvh;                         ts.Tl[0] = wqkvl;
    ts.W[1] = Wk; ts.Th[1] = wqkvh + D_MODEL * D_MODEL;     ts.Tl[1] = wqkvl + D_MODEL * D_MODEL;
    ts.W[2] = Wv; ts.Th[2] = wqkvh + 2 * D_MODEL * D_MODEL; ts.Tl[2] = wqkvl + 2 * D_MODEL * D_MODEL;
    transpose_split3_kernel<<<dim3(32, 32, 3), blk, 0, s3>>>(ts);
    cudaEventRecord(evJoin3, s3);

    // chunk streams: (p,c): (0,0)->0, (0,1)->s2, (1,0)->s4, (1,1)->s3
    cudaStream_t cs[2][2] = {{(cudaStream_t)0, s2}, {s4, s3}};
    cudaEvent_t evQ[2] = {evQ0, evQ1};
    cudaEvent_t evA[2] = {evA0, evA1};
    // attention runs on the c=0 stream of each batch

    // per-chunk grids (Mq = 1024 rows)
    dim3 grid_qkv(3 * D_MODEL / 128, Mq / 128);   // (24, 8)
    dim3 grid_d(D_MODEL / 128, Mq / 128);         // (8, 8)
    dim3 grid_f(FF_DIM / 128,  Mq / 128);         // (32, 8)
    dim3 agrid(L / 128, HEADS);                   // (16, 16) per batch
    const int splitn4 = Mq * D_MODEL / 4;

    // ---- phase 1: per-chunk split + QKV ----
    for (int p = 0; p < 2; p++) {
        for (int c = 0; c < 2; c++) {
            cudaStream_t st = cs[p][c];
            const size_t od = ((size_t)p * Mh + (size_t)c * Mq) * D_MODEL;
            split_kernel<<<(splitn4 + 255) / 256, blk, 0, st>>>(x + od, xh + od, xl + od, splitn4);
            cudaStreamWaitEvent(st, evJoin3, 0);
            gemm_tc_kernel<<<grid_qkv, blk, GEMM_SMEM_BYTES, st>>>(
                xh + od, xl + od, wqkvh, wqkvl, bqkv, nullptr,
                qh + od, ql + od, kh + od, kl + od, vh + od, vl + od,
                Mq, 3 * D_MODEL, D_MODEL, 0);
            if (c == 1) cudaEventRecord(evQ[p], st);
        }
    }

    // ---- phase 2: attention per batch (joins both chunks) ----
    for (int p = 0; p < 2; p++) {
        cudaStream_t st = cs[p][0];
        cudaStreamWaitEvent(st, evQ[p], 0);
        const size_t ob = (size_t)p * Mh * D_MODEL;
        attn_tc_kernel<<<agrid, blk, ATTN_SMEM, st>>>(
            qh + ob, ql + ob, kh + ob, kl + ob, vh + ob, vl + ob,
            ah + ob, al + ob, L);
        cudaEventRecord(evA[p], st);
    }

    // ---- phase 3: per-chunk proj + LN1 + FFN + LN2 ----
    for (int p = 0; p < 2; p++) {
        for (int c = 0; c < 2; c++) {
            cudaStream_t st = cs[p][c];
            if (c == 1) cudaStreamWaitEvent(st, evA[p], 0);
            cudaStreamWaitEvent(st, evJoin2, 0);
            const size_t od = ((size_t)p * Mh + (size_t)c * Mq) * D_MODEL;
            const size_t of = ((size_t)p * Mh + (size_t)c * Mq) * FF_DIM;

            gemm_tc_kernel<<<grid_d, blk, GEMM_SMEM_BYTES, st>>>(
                ah + od, al + od, wmh, wml, bm, proj + od,
                nullptr, nullptr, nullptr, nullptr, nullptr, nullptr,
                Mq, D_MODEL, D_MODEL, 0);
            ln_residual_kernel<<<Mq, blk, 0, st>>>(x + od, proj + od, g1, be1,
                                                   h + od, hh + od, hl + od);
            gemm_tc_kernel<<<grid_f, blk, GEMM_SMEM_BYTES, st>>>(
                hh + od, hl + od, w1h, w1l, b1, nullptr,
                ffh + of, ffl + of, nullptr, nullptr, nullptr, nullptr,
                Mq, FF_DIM, D_MODEL, 1);
            gemm_tc_kernel<<<grid_d, blk, GEMM_SMEM_BYTES, st>>>(
                ffh + of, ffl + of, w2h, w2l, b2, tmp + od,
                nullptr, nullptr, nullptr, nullptr, nullptr, nullptr,
                Mq, D_MODEL, FF_DIM, 0);
            ln_residual_kernel<<<Mq, blk, 0, st>>>(h + od, tmp + od, g2, be2,
                                                   out + od, nullptr, nullptr);
        }
    }

    // ---- join all side streams back into the capture stream ----
    cudaEventRecord(evD2, s2);
    cudaEventRecord(evD3, s3);
    cudaEventRecord(evD4, s4);
    cudaStreamWaitEvent(0, evD2, 0);
    cudaStreamWaitEvent(0, evD3, 0);
    cudaStreamWaitEvent(0, evD4, 0);
}

// round 17
// speedup vs baseline: 1.0335x; 1.0335x over previous
#include <cuda_runtime.h>
#include <cuda_bf16.h>
#include <math.h>
#include <stdint.h>

// ---------------------------------------------------------------------------
// Fixed problem shape
// ---------------------------------------------------------------------------
#define D_MODEL 1024
#define HEADS   16
#define HEAD_DIM 64
#define FF_DIM  4096
#define SEQ_L   2048
#define EPS     1e-5f
#define MROWS   4096      // B * L

// ---------------------------------------------------------------------------
// Scratch (static device globals; no runtime allocation allowed)
// ---------------------------------------------------------------------------
__device__ float g_proj[MROWS * D_MODEL];
__device__ float g_h   [MROWS * D_MODEL];
__device__ float g_tmp [MROWS * D_MODEL];
__device__ float g_bqkv[3 * D_MODEL];

// split activations (bf16 hi/lo)
__device__ __nv_bfloat16 g_xh[MROWS * D_MODEL];
__device__ __nv_bfloat16 g_xl[MROWS * D_MODEL];
__device__ __nv_bfloat16 g_qh[MROWS * D_MODEL];
__device__ __nv_bfloat16 g_ql[MROWS * D_MODEL];
__device__ __nv_bfloat16 g_kh[MROWS * D_MODEL];
__device__ __nv_bfloat16 g_kl[MROWS * D_MODEL];
__device__ __nv_bfloat16 g_vh[MROWS * D_MODEL];
__device__ __nv_bfloat16 g_vl[MROWS * D_MODEL];
__device__ __nv_bfloat16 g_ah[MROWS * D_MODEL];
__device__ __nv_bfloat16 g_al[MROWS * D_MODEL];
__device__ __nv_bfloat16 g_hh[MROWS * D_MODEL];
__device__ __nv_bfloat16 g_hl[MROWS * D_MODEL];
__device__ __nv_bfloat16 g_ffh[MROWS * FF_DIM];
__device__ __nv_bfloat16 g_ffl[MROWS * FF_DIM];

// weights: QKV concatenated [3072][1024]; Wm; W1; W2 (all [N][K] bf16 hi/lo)
__device__ __nv_bfloat16 g_wqkv_h[3 * D_MODEL * D_MODEL];
__device__ __nv_bfloat16 g_wqkv_l[3 * D_MODEL * D_MODEL];
__device__ __nv_bfloat16 g_wm_h[D_MODEL * D_MODEL];
__device__ __nv_bfloat16 g_wm_l[D_MODEL * D_MODEL];
__device__ __nv_bfloat16 g_w1_h[D_MODEL * FF_DIM];
__device__ __nv_bfloat16 g_w1_l[D_MODEL * FF_DIM];
__device__ __nv_bfloat16 g_w2_h[FF_DIM * D_MODEL];
__device__ __nv_bfloat16 g_w2_l[FF_DIM * D_MODEL];

// ---------------------------------------------------------------------------
// Helpers (base sm_100-safe: ldmatrix + mma.sync + cp.async)
// ---------------------------------------------------------------------------
__device__ __forceinline__ uint32_t smem_u32(const void* p) {
    uint32_t a;
    asm("{ .reg .u64 t; cvta.to.shared.u64 t, %1; cvt.u32.u64 %0, t; }" : "=r"(a) : "l"(p));
    return a;
}
__device__ __forceinline__ void ldsm4(uint32_t* r, uint32_t addr) {
    asm volatile("ldmatrix.sync.aligned.m8n8.x4.shared.b16 {%0,%1,%2,%3}, [%4];"
                 : "=r"(r[0]), "=r"(r[1]), "=r"(r[2]), "=r"(r[3]) : "r"(addr));
}
__device__ __forceinline__ void ldsm4t(uint32_t* r, uint32_t addr) {
    asm volatile("ldmatrix.sync.aligned.m8n8.x4.trans.shared.b16 {%0,%1,%2,%3}, [%4];"
                 : "=r"(r[0]), "=r"(r[1]), "=r"(r[2]), "=r"(r[3]) : "r"(addr));
}
__device__ __forceinline__ void mma16816(float* d, const uint32_t* a, const uint32_t* b) {
    asm volatile("mma.sync.aligned.m16n8k16.row.col.f32.bf16.bf16.f32 "
                 "{%0,%1,%2,%3}, {%4,%5,%6,%7}, {%8,%9}, {%0,%1,%2,%3};"
                 : "+f"(d[0]), "+f"(d[1]), "+f"(d[2]), "+f"(d[3])
                 : "r"(a[0]), "r"(a[1]), "r"(a[2]), "r"(a[3]), "r"(b[0]), "r"(b[1]));
}
__device__ __forceinline__ void cp_async16(uint32_t saddr, const void* gptr) {
    asm volatile("cp.async.cg.shared.global [%0], [%1], 16;"
                 :: "r"(saddr), "l"(gptr) : "memory");
}
__device__ __forceinline__ void cp_commit() {
    asm volatile("cp.async.commit_group;" ::: "memory");
}
template<int N> __device__ __forceinline__ void cp_wait() {
    asm volatile("cp.async.wait_group %0;" :: "n"(N) : "memory");
}
__device__ __forceinline__ uint32_t packbf(float a, float b) {
    __nv_bfloat162 t = __float22bfloat162_rn(make_float2(a, b));
    return *reinterpret_cast<uint32_t*>(&t);
}
__device__ __forceinline__ float2 unpackbf(uint32_t u) {
    return __bfloat1622float2(*reinterpret_cast<__nv_bfloat162*>(&u));
}

// ---------------------------------------------------------------------------
// Weight transpose + hi/lo split: W[K,N] fp32 -> Th/Tl[N,K] bf16
// 64(K) x 32(N) tile; loads and stores both fully coalesced (128B/warp).
// ---------------------------------------------------------------------------
__global__ __launch_bounds__(256) void transpose_split_kernel(
    const float* __restrict__ W, __nv_bfloat16* __restrict__ Th,
    __nv_bfloat16* __restrict__ Tl, int K, int N)
{
    __shared__ float t[32][65];           // [n][k]
    const int n0 = blockIdx.x * 32, k0 = blockIdx.y * 64;
    const int nn = threadIdx.x & 31, kk = threadIdx.x >> 5;   // kk 0..7
#pragma unroll
    for (int i = 0; i < 8; i++)
        t[nn][kk + i * 8] = W[(size_t)(k0 + kk + i * 8) * N + n0 + nn];
    __syncthreads();
    const int kp = threadIdx.x & 31;      // k-pair 0..31 -> k = 2kp, 2kp+1
    const int nr = threadIdx.x >> 5;      // 0..7
#pragma unroll
    for (int i = 0; i < 4; i++) {
        const int n = nr + i * 8;
        const float v0 = t[n][2 * kp];
        const float v1 = t[n][2 * kp + 1];
        const uint32_t h = packbf(v0, v1);
        const float2 f = unpackbf(h);
        const uint32_t l = packbf(v0 - f.x, v1 - f.y);
        const size_t o = ((size_t)(n0 + n) * K + k0) / 2 + kp;  // uint32 units
        ((uint32_t*)Th)[o] = h;
        ((uint32_t*)Tl)[o] = l;
    }
}

// 3 square DxD transposes in one launch (grid.z selects matrix) — QKV weights
struct TS3 {
    const float* W[3];
    __nv_bfloat16* Th[3];
    __nv_bfloat16* Tl[3];
};
__global__ __launch_bounds__(256) void transpose_split3_kernel(TS3 a)
{
    __shared__ float t[32][65];
    const int m = blockIdx.z;
    const float* W = a.W[m];
    __nv_bfloat16* Th = a.Th[m];
    __nv_bfloat16* Tl = a.Tl[m];
    const int n0 = blockIdx.x * 32, k0 = blockIdx.y * 64;
    const int nn = threadIdx.x & 31, kk = threadIdx.x >> 5;
#pragma unroll
    for (int i = 0; i < 8; i++)
        t[nn][kk + i * 8] = W[(size_t)(k0 + kk + i * 8) * D_MODEL + n0 + nn];
    __syncthreads();
    const int kp = threadIdx.x & 31;
    const int nr = threadIdx.x >> 5;
#pragma unroll
    for (int i = 0; i < 4; i++) {
        const int n = nr + i * 8;
        const float v0 = t[n][2 * kp];
        const float v1 = t[n][2 * kp + 1];
        const uint32_t h = packbf(v0, v1);
        const float2 f = unpackbf(h);
        const uint32_t l = packbf(v0 - f.x, v1 - f.y);
        const size_t o = ((size_t)(n0 + n) * D_MODEL + k0) / 2 + kp;
        ((uint32_t*)Th)[o] = h;
        ((uint32_t*)Tl)[o] = l;
    }
}

// ---------------------------------------------------------------------------
// Elementwise hi/lo split: x fp32 -> xh, xl bf16
// ---------------------------------------------------------------------------
__global__ __launch_bounds__(256) void split_kernel(
    const float* __restrict__ x, __nv_bfloat16* __restrict__ xh,
    __nv_bfloat16* __restrict__ xl, int n4)
{
    int i = blockIdx.x * 256 + threadIdx.x;
    if (i >= n4) return;
    float4 v = *(const float4*)(x + (size_t)i * 4);
    uint32_t h0 = packbf(v.x, v.y), h1 = packbf(v.z, v.w);
    float2 f0 = unpackbf(h0), f1 = unpackbf(h1);
    uint32_t l0 = packbf(v.x - f0.x, v.y - f0.y);
    uint32_t l1 = packbf(v.z - f1.x, v.w - f1.y);
    *(uint2*)((char*)xh + (size_t)i * 8) = make_uint2(h0, h1);
    *(uint2*)((char*)xl + (size_t)i * 8) = make_uint2(l0, l1);
}

// ---------------------------------------------------------------------------
// HMMA GEMM, 3-stage cp.async pipeline, 2 CTAs/SM (128-reg cap).
// If Ch1 != null: fused-QKV mode (N spans 3 concatenated outputs).
// ---------------------------------------------------------------------------
#define TBK 32
#define STAGE_BYTES 32768
#define NSTAGE 3
#define GEMM_SMEM_BYTES (NSTAGE * STAGE_BYTES)   // 96KB/CTA; 2 CTAs = 192KB/SM

__global__ __launch_bounds__(256, 2)
void gemm_tc_kernel(const __nv_bfloat16* __restrict__ Ah,
                    const __nv_bfloat16* __restrict__ Al,
                    const __nv_bfloat16* __restrict__ BTh,
                    const __nv_bfloat16* __restrict__ BTl,
                    const float* __restrict__ bias,
                    float* __restrict__ Cf,
                    __nv_bfloat16* __restrict__ Ch,
                    __nv_bfloat16* __restrict__ Cl,
                    __nv_bfloat16* __restrict__ Ch1,
                    __nv_bfloat16* __restrict__ Cl1,
                    __nv_bfloat16* __restrict__ Ch2,
                    __nv_bfloat16* __restrict__ Cl2,
                    int M, int N, int K, int relu)
{
    extern __shared__ char smem[];
    const uint32_t sb = smem_u32(smem);

    const int tid = threadIdx.x;
    const int wid = tid >> 5;
    const int lane = tid & 31;
    const int row0 = blockIdx.y * 128;
    const int col0 = blockIdx.x * 128;
    const int wm0 = (wid & 3) * 32;
    const int wn0 = (wid >> 2) * 64;
    const int nkb = K / TBK;

    const int sr = tid >> 3;
    const int sj = tid & 7;
    const __nv_bfloat16* Asrc = (sj < 4) ? Ah : Al;
    const __nv_bfloat16* Bsrc = (sj < 4) ? BTh : BTl;
    const int sk = (sj & 3) * 8;

    const int lr = lane & 7;
    const int mh = (lane >> 3) & 1;
    const int kh = (lane >> 4) & 1;
    uint32_t aRow[2], bN[4];
#pragma unroll
    for (int mt = 0; mt < 2; mt++) aRow[mt] = wm0 + mt * 16 + mh * 8 + lr;
#pragma unroll
    for (int g = 0; g < 4; g++)    bN[g]   = wn0 + g * 16 + kh * 8 + lr;

    float acc[2][8][4];
#pragma unroll
    for (int mt = 0; mt < 2; mt++)
#pragma unroll
        for (int nt = 0; nt < 8; nt++)
#pragma unroll
            for (int i = 0; i < 4; i++) acc[mt][nt][i] = 0.f;

    auto issue = [&](int kb) {
        const int s = kb % NSTAGE;
        const uint32_t Ab = sb + s * STAGE_BYTES;
        const uint32_t Bb = Ab + 16384;
#pragma unroll
        for (int it = 0; it < 4; it++) {
            const int r = sr + it * 32;
            const uint32_t off = r * 128 + ((sj ^ (r & 7)) << 4);
            cp_async16(Ab + off, Asrc + (size_t)(row0 + r) * K + kb * TBK + sk);
            cp_async16(Bb + off, Bsrc + (size_t)(col0 + r) * K + kb * TBK + sk);
        }
    };
    auto compute = [&](int s) {
        const uint32_t Ab = sb + s * STAGE_BYTES;
        const uint32_t Bb = Ab + 16384;
#pragma unroll
        for (int kc = 0; kc < 2; kc++) {
            uint32_t ah[2][4], al[2][4];
#pragma unroll
            for (int mt = 0; mt < 2; mt++) {
                const uint32_t ra = Ab + aRow[mt] * 128;
                const int sw = aRow[mt] & 7;
                ldsm4(ah[mt], ra + (((kc * 2 + kh    ) ^ sw) << 4));
                ldsm4(al[mt], ra + (((kc * 2 + kh + 4) ^ sw) << 4));
            }
#pragma unroll
            for (int g = 0; g < 4; g++) {
                const uint32_t rb = Bb + bN[g] * 128;
                const int sw = bN[g] & 7;
                uint32_t bh[4], bl[4];
                ldsm4(bh, rb + (((kc * 2 + mh    ) ^ sw) << 4));
                ldsm4(bl, rb + (((kc * 2 + mh + 4) ^ sw) << 4));
                mma16816(acc[0][2 * g],     ah[0], bh);
                mma16816(acc[1][2 * g],     ah[1], bh);
                mma16816(acc[0][2 * g + 1], ah[0], bh + 2);
                mma16816(acc[1][2 * g + 1], ah[1], bh + 2);
                mma16816(acc[0][2 * g],     ah[0], bl);
                mma16816(acc[1][2 * g],     ah[1], bl);
                mma16816(acc[0][2 * g + 1], ah[0], bl + 2);
                mma16816(acc[1][2 * g + 1], ah[1], bl + 2);
                mma16816(acc[0][2 * g],     al[0], bh);
                mma16816(acc[1][2 * g],     al[1], bh);
                mma16816(acc[0][2 * g + 1], al[0], bh + 2);
                mma16816(acc[1][2 * g + 1], al[1], bh + 2);
            }
        }
    };

    issue(0); cp_commit();
    issue(1); cp_commit();
    for (int kb = 0; kb < nkb; kb++) {
        if (kb + 1 < nkb) cp_wait<1>(); else cp_wait<0>();
        __syncthreads();
        if (kb + 2 < nkb) { issue(kb + 2); cp_commit(); }
        compute(kb % NSTAGE);
    }

    // epilogue (QKV mode: select output by column block)
    __nv_bfloat16* po_h = Ch;
    __nv_bfloat16* po_l = Cl;
    int outN = N;
    int ocol0 = col0;
    if (Ch1) {
        const int which = col0 >> 10;
        po_h = (which == 0) ? Ch : ((which == 1) ? Ch1 : Ch2);
        po_l = (which == 0) ? Cl : ((which == 1) ? Cl1 : Cl2);
        outN = D_MODEL;
        ocol0 = col0 - (which << 10);
    }
    const int qr = lane >> 2;
    const int qc = (lane & 3) * 2;
#pragma unroll
    for (int mt = 0; mt < 2; mt++) {
#pragma unroll
        for (int nt = 0; nt < 8; nt++) {
            const int r = row0 + wm0 + mt * 16 + qr;
            const int cg = col0 + wn0 + nt * 8 + qc;     // bias index
            const int c  = ocol0 + wn0 + nt * 8 + qc;    // output col
            const float b0 = bias[cg], b1 = bias[cg + 1];
            float v0 = acc[mt][nt][0] + b0;
            float v1 = acc[mt][nt][1] + b1;
            float v2 = acc[mt][nt][2] + b0;
            float v3 = acc[mt][nt][3] + b1;
            if (relu) {
                v0 = fmaxf(v0, 0.f); v1 = fmaxf(v1, 0.f);
                v2 = fmaxf(v2, 0.f); v3 = fmaxf(v3, 0.f);
            }
            if (Cf) {
                *(float2*)(Cf + (size_t)r * N + c) = make_float2(v0, v1);
                *(float2*)(Cf + (size_t)(r + 8) * N + c) = make_float2(v2, v3);
            }
            if (po_h) {
                uint32_t h0 = packbf(v0, v1);
                uint32_t h1 = packbf(v2, v3);
                float2 f0 = unpackbf(h0), f1 = unpackbf(h1);
                uint32_t l0 = packbf(v0 - f0.x, v1 - f0.y);
                uint32_t l1 = packbf(v2 - f1.x, v3 - f1.y);
                *(uint32_t*)((char*)po_h + ((size_t)r * outN + c) * 2) = h0;
                *(uint32_t*)((char*)po_h + ((size_t)(r + 8) * outN + c) * 2) = h1;
                *(uint32_t*)((char*)po_l + ((size_t)r * outN + c) * 2) = l0;
                *(uint32_t*)((char*)po_l + ((size_t)(r + 8) * outN + c) * 2) = l1;
            }
        }
    }
}

// ---------------------------------------------------------------------------
// Flash-attention with HMMA (split-3 bf16, fp32 accum), cp.async staging.
// 2 CTAs/SM. grid.y = 2*HEADS over the full M (batch via blockIdx.y / HEADS).
// ---------------------------------------------------------------------------
#define ATTN_SMEM 98304

__global__ __launch_bounds__(256, 2)
void attn_tc_kernel(const __nv_bfloat16* __restrict__ qh, const __nv_bfloat16* __restrict__ ql,
                    const __nv_bfloat16* __restrict__ kh_g, const __nv_bfloat16* __restrict__ kl_g,
                    const __nv_bfloat16* __restrict__ vh_g, const __nv_bfloat16* __restrict__ vl_g,
                    __nv_bfloat16* __restrict__ oh, __nv_bfloat16* __restrict__ ol, int L)
{
    extern __shared__ char smem[];
    const uint32_t sb = smem_u32(smem);
    const uint32_t qoff = sb;
    const uint32_t koff = sb + 32768;
    const uint32_t voff = sb + 65536;

    const int tid = threadIdx.x;
    const int wid = tid >> 5;
    const int lane = tid & 31;
    const int bh_ = blockIdx.y;
    const int b = bh_ / HEADS;
    const int hd = (bh_ % HEADS) * HEAD_DIM;
    const int l0 = blockIdx.x * 128;
    const int tok0 = b * L + l0;
    const int kbase = b * L;

    const int lr = lane & 7;
    const int mh = (lane >> 3) & 1;
    const int khb = (lane >> 4) & 1;

    auto issueKV = [&](int kb) {
        const int t0 = kbase + kb * 64;
        const int s = kb & 1;
        const uint32_t kb_ = koff + s * 16384;
        const uint32_t vb_ = voff + s * 16384;
#pragma unroll
        for (int it = 0; it < 4; it++) {
            int id = it * 256 + tid;
            {
                int c = id >> 9, row = (id >> 3) & 63, j = id & 7;
                const __nv_bfloat16* src = (j < 4) ? kh_g : kl_g;
                cp_async16(kb_ + c * 8192 + row * 128 + ((j ^ (row & 7)) << 4),
                           src + (size_t)(t0 + row) * D_MODEL + hd + c * 32 + (j & 3) * 8);
            }
            {
                int row = (id >> 3) & 63, j = id & 7;
                const __nv_bfloat16* src = (id < 512) ? vh_g : vl_g;
                cp_async16(vb_ + ((id < 512) ? 0 : 8192) + row * 128 + ((j ^ (row & 7)) << 4),
                           src + (size_t)(t0 + row) * D_MODEL + hd + j * 8);
            }
        }
    };

#pragma unroll
    for (int it = 0; it < 8; it++) {
        int id = it * 256 + tid;
        int c = id >> 10, rem = id & 1023;
        int row = rem >> 3, j = rem & 7;
        const __nv_bfloat16* src = (j < 4) ? qh : ql;
        cp_async16(qoff + c * 16384 + row * 128 + ((j ^ (row & 7)) << 4),
                   src + (size_t)(tok0 + row) * D_MODEL + hd + c * 32 + (j & 3) * 8);
    }
    cp_commit();
    issueKV(0); cp_commit();
    cp_wait<0>();
    __syncthreads();

    const int aRow = wid * 16 + mh * 8 + lr;
    const int asw = aRow & 7;

    float m0 = -3.0e38f, m1 = -3.0e38f, li0 = 0.f, li1 = 0.f;
    float oacc[8][4];
#pragma unroll
    for (int j = 0; j < 8; j++)
#pragma unroll
        for (int i = 0; i < 4; i++) oacc[j][i] = 0.f;

    const int nkb = L / 64;
    for (int kb = 0; kb < nkb; kb++) {
        const int s = kb & 1;
        if (kb) {
            cp_wait<0>();
            __syncthreads();
        }
        if (kb + 1 < nkb) { issueKV(kb + 1); cp_commit(); }

        // ---- S = Q @ K^T ----
        float sacc[8][4];
#pragma unroll
        for (int j = 0; j < 8; j++)
#pragma unroll
            for (int i = 0; i < 4; i++) sacc[j][i] = 0.f;

        const uint32_t kst = koff + s * 16384;
#pragma unroll
        for (int c = 0; c < 2; c++) {
            const uint32_t qbase = qoff + c * 16384 + aRow * 128;
#pragma unroll
            for (int kc = 0; kc < 2; kc++) {
                uint32_t qah[4], qal[4];
                ldsm4(qah, qbase + (((kc * 2 + khb    ) ^ asw) << 4));
                ldsm4(qal, qbase + (((kc * 2 + khb + 4) ^ asw) << 4));
#pragma unroll
                for (int g = 0; g < 4; g++) {
                    const int bN = g * 16 + khb * 8 + lr;
                    const int sw = bN & 7;
                    const uint32_t rb = kst + c * 8192 + bN * 128;
                    uint32_t kbh[4], kbl[4];
                    ldsm4(kbh, rb + (((kc * 2 + mh    ) ^ sw) << 4));
                    ldsm4(kbl, rb + (((kc * 2 + mh + 4) ^ sw) << 4));
                    mma16816(sacc[2 * g],     qah, kbh);
                    mma16816(sacc[2 * g + 1], qah, kbh + 2);
                    mma16816(sacc[2 * g],     qah, kbl);
                    mma16816(sacc[2 * g + 1], qah, kbl + 2);
                    mma16816(sacc[2 * g],     qal, kbh);
                    mma16816(sacc[2 * g + 1], qal, kbh + 2);
                }
            }
        }

        // ---- online softmax ----
#pragma unroll
        for (int j = 0; j < 8; j++)
#pragma unroll
            for (int i = 0; i < 4; i++) sacc[j][i] *= 0.125f;

        float mx0 = -3.0e38f, mx1 = -3.0e38f;
#pragma unroll
        for (int j = 0; j < 8; j++) {
            mx0 = fmaxf(mx0, fmaxf(sacc[j][0], sacc[j][1]));
            mx1 = fmaxf(mx1, fmaxf(sacc[j][2], sacc[j][3]));
        }
        mx0 = fmaxf(mx0, __shfl_xor_sync(0xffffffffu, mx0, 1));
        mx0 = fmaxf(mx0, __shfl_xor_sync(0xffffffffu, mx0, 2));
        mx1 = fmaxf(mx1, __shfl_xor_sync(0xffffffffu, mx1, 1));
        mx1 = fmaxf(mx1, __shfl_xor_sync(0xffffffffu, mx1, 2));
        const float mn0 = fmaxf(m0, mx0);
        const float mn1 = fmaxf(m1, mx1);
        const float co0 = __expf(m0 - mn0);
        const float co1 = __expf(m1 - mn1);
        float rs0 = 0.f, rs1 = 0.f;
#pragma unroll
        for (int j = 0; j < 8; j++) {
            sacc[j][0] = __expf(sacc[j][0] - mn0);
            sacc[j][1] = __expf(sacc[j][1] - mn0);
            sacc[j][2] = __expf(sacc[j][2] - mn1);
            sacc[j][3] = __expf(sacc[j][3] - mn1);
            rs0 += sacc[j][0] + sacc[j][1];
            rs1 += sacc[j][2] + sacc[j][3];
        }
        rs0 += __shfl_xor_sync(0xffffffffu, rs0, 1);
        rs0 += __shfl_xor_sync(0xffffffffu, rs0, 2);
        rs1 += __shfl_xor_sync(0xffffffffu, rs1, 1);
        rs1 += __shfl_xor_sync(0xffffffffu, rs1, 2);
        li0 = li0 * co0 + rs0;
        li1 = li1 * co1 + rs1;
        m0 = mn0; m1 = mn1;
#pragma unroll
        for (int j = 0; j < 8; j++) {
            oacc[j][0] *= co0; oacc[j][1] *= co0;
            oacc[j][2] *= co1; oacc[j][3] *= co1;
        }

        // ---- O += P @ V ----
        const uint32_t vst = voff + s * 16384;
#pragma unroll
        for (int t = 0; t < 4; t++) {
            const int j0 = 2 * t, j1 = 2 * t + 1;
            uint32_t ph[4], pl[4];
            ph[0] = packbf(sacc[j0][0], sacc[j0][1]);
            ph[1] = packbf(sacc[j0][2], sacc[j0][3]);
            ph[2] = packbf(sacc[j1][0], sacc[j1][1]);
            ph[3] = packbf(sacc[j1][2], sacc[j1][3]);
#pragma unroll
            for (int i = 0; i < 4; i++) {
                float2 f = unpackbf(ph[i]);
                const float* sp = (i < 2) ? sacc[j0] : sacc[j1];
                int o = (i & 1) * 2;
                pl[i] = packbf(sp[o] - f.x, sp[o + 1] - f.y);
            }
            const int vRow = t * 16 + mh * 8 + lr;
            const int sw = vRow & 7;
            const uint32_t vrb = vst + vRow * 128;
#pragma unroll
            for (int g = 0; g < 4; g++) {
                uint32_t vvh[4], vvl[4];
                ldsm4t(vvh, vrb + (((g * 2 + khb) ^ sw) << 4));
                ldsm4t(vvl, vrb + 8192 + (((g * 2 + khb) ^ sw) << 4));
                mma16816(oacc[2 * g],     ph, vvh);
                mma16816(oacc[2 * g + 1], ph, vvh + 2);
                mma16816(oacc[2 * g],     ph, vvl);
                mma16816(oacc[2 * g + 1], ph, vvl + 2);
                mma16816(oacc[2 * g],     pl, vvh);
                mma16816(oacc[2 * g + 1], pl, vvh + 2);
            }
        }
    }

    // ---- epilogue ----
    const float inv0 = 1.f / li0;
    const float inv1 = 1.f / li1;
    const int r0 = tok0 + wid * 16 + (lane >> 2);
    const int r1 = r0 + 8;
#pragma unroll
    for (int j = 0; j < 8; j++) {
        const int c = hd + j * 8 + (lane & 3) * 2;
        float v0 = oacc[j][0] * inv0, v1 = oacc[j][1] * inv0;
        float v2 = oacc[j][2] * inv1, v3 = oacc[j][3] * inv1;
        uint32_t h0 = packbf(v0, v1), h1 = packbf(v2, v3);
        float2 f0 = unpackbf(h0), f1 = unpackbf(h1);
        uint32_t lo0 = packbf(v0 - f0.x, v1 - f0.y);
        uint32_t lo1 = packbf(v2 - f1.x, v3 - f1.y);
        *(uint32_t*)((char*)oh + ((size_t)r0 * D_MODEL + c) * 2) = h0;
        *(uint32_t*)((char*)ol + ((size_t)r0 * D_MODEL + c) * 2) = lo0;
        *(uint32_t*)((char*)oh + ((size_t)r1 * D_MODEL + c) * 2) = h1;
        *(uint32_t*)((char*)ol + ((size_t)r1 * D_MODEL + c) * 2) = lo1;
    }
}

// ---------------------------------------------------------------------------
// Fused residual + LayerNorm (+ optional split bf16 outputs)
// ---------------------------------------------------------------------------
__global__ __launch_bounds__(256) void ln_residual_kernel(
    const float* __restrict__ a, const float* __restrict__ r,
    const float* __restrict__ g, const float* __restrict__ beta,
    float* __restrict__ out, __nv_bfloat16* __restrict__ outh,
    __nv_bfloat16* __restrict__ outl)
{
    __shared__ float red[8];
    const int row = blockIdx.x;
    const int tid = threadIdx.x;
    const int lane = tid & 31, warp = tid >> 5;
    const size_t off = (size_t)row * D_MODEL + tid * 4;

    float4 va = *(const float4*)(a + off);
    float4 vr = *(const float4*)(r + off);
    float x[4] = {va.x + vr.x, va.y + vr.y, va.z + vr.z, va.w + vr.w};

    float sum = x[0] + x[1] + x[2] + x[3];
#pragma unroll
    for (int o = 16; o; o >>= 1) sum += __shfl_down_sync(0xffffffffu, sum, o);
    if (lane == 0) red[warp] = sum;
    __syncthreads();
    if (warp == 0) {
        float v = (lane < 8) ? red[lane] : 0.f;
#pragma unroll
        for (int o = 4; o; o >>= 1) v += __shfl_down_sync(0xffu, v, o);
        if (lane == 0) red[0] = v;
    }
    __syncthreads();
    const float mu = red[0] * (1.f / D_MODEL);
    __syncthreads();

    float sq = 0.f;
#pragma unroll
    for (int i = 0; i < 4; i++) {
        float d = x[i] - mu;
        sq += d * d;
    }
#pragma unroll
    for (int o = 16; o; o >>= 1) sq += __shfl_down_sync(0xffffffffu, sq, o);
    if (lane == 0) red[warp] = sq;
    __syncthreads();
    if (warp == 0) {
        float v = (lane < 8) ? red[lane] : 0.f;
#pragma unroll
        for (int o = 4; o; o >>= 1) v += __shfl_down_sync(0xffu, v, o);
        if (lane == 0) red[0] = v;
    }
    __syncthreads();
    const float rstd = rsqrtf(red[0] * (1.f / D_MODEL) + EPS);

    float4 gg = *(const float4*)(g + tid * 4);
    float4 bb = *(const float4*)(beta + tid * 4);
    float y[4];
    y[0] = (x[0] - mu) * rstd * gg.x + bb.x;
    y[1] = (x[1] - mu) * rstd * gg.y + bb.y;
    y[2] = (x[2] - mu) * rstd * gg.z + bb.z;
    y[3] = (x[3] - mu) * rstd * gg.w + bb.w;
    *(float4*)(out + off) = *(float4*)&y[0];
    if (outh) {
        uint32_t h0 = packbf(y[0], y[1]), h1 = packbf(y[2], y[3]);
        float2 f0 = unpackbf(h0), f1 = unpackbf(h1);
        uint32_t l0 = packbf(y[0] - f0.x, y[1] - f0.y);
        uint32_t l1 = packbf(y[2] - f1.x, y[3] - f1.y);
        *(uint2*)((char*)outh + off * 2) = make_uint2(h0, h1);
        *(uint2*)((char*)outl + off * 2) = make_uint2(l0, l1);
    }
}

// ---------------------------------------------------------------------------
// Launch sequence: per-batch pipelines on 2 streams + weight-prep side streams
// (the R12 winner structure, with the improved transpose kernels)
// ---------------------------------------------------------------------------
extern "C" void kernel_launch(void* const* d_in, const int* in_sizes, int n_in,
                              void* d_out, int out_size)
{
    const float* x  = (const float*)d_in[0];
    const float* Wq = (const float*)d_in[1];
    const float* bq = (const float*)d_in[2];
    const float* Wk = (const float*)d_in[3];
    const float* bk = (const float*)d_in[4];
    const float* Wv = (const float*)d_in[5];
    const float* bv = (const float*)d_in[6];
    const float* Wm = (const float*)d_in[7];
    const float* bm = (const float*)d_in[8];
    const float* W1 = (const float*)d_in[9];
    const float* b1 = (const float*)d_in[10];
    const float* W2 = (const float*)d_in[11];
    const float* b2 = (const float*)d_in[12];
    const float* g1  = (const float*)d_in[13];
    const float* be1 = (const float*)d_in[14];
    const float* g2  = (const float*)d_in[15];
    const float* be2 = (const float*)d_in[16];
    float* out = (float*)d_out;

    const int M = in_sizes[0] / D_MODEL;   // 4096
    const int L = SEQ_L;
    const int Mh = M / 2;                  // rows per batch = 2048

    float *proj, *h, *tmp, *bqkv;
    cudaGetSymbolAddress((void**)&proj, g_proj);
    cudaGetSymbolAddress((void**)&h,    g_h);
    cudaGetSymbolAddress((void**)&tmp,  g_tmp);
    cudaGetSymbolAddress((void**)&bqkv, g_bqkv);

    __nv_bfloat16 *xh, *xl, *qh, *ql, *kh, *kl, *vh, *vl, *ah, *al, *hh, *hl, *ffh, *ffl;
    cudaGetSymbolAddress((void**)&xh, g_xh); cudaGetSymbolAddress((void**)&xl, g_xl);
    cudaGetSymbolAddress((void**)&qh, g_qh); cudaGetSymbolAddress((void**)&ql, g_ql);
    cudaGetSymbolAddress((void**)&kh, g_kh); cudaGetSymbolAddress((void**)&kl, g_kl);
    cudaGetSymbolAddress((void**)&vh, g_vh); cudaGetSymbolAddress((void**)&vl, g_vl);
    cudaGetSymbolAddress((void**)&ah, g_ah); cudaGetSymbolAddress((void**)&al, g_al);
    cudaGetSymbolAddress((void**)&hh, g_hh); cudaGetSymbolAddress((void**)&hl, g_hl);
    cudaGetSymbolAddress((void**)&ffh, g_ffh); cudaGetSymbolAddress((void**)&ffl, g_ffl);

    __nv_bfloat16 *wqkvh, *wqkvl, *wmh, *wml, *w1h, *w1l, *w2h, *w2l;
    cudaGetSymbolAddress((void**)&wqkvh, g_wqkv_h); cudaGetSymbolAddress((void**)&wqkvl, g_wqkv_l);
    cudaGetSymbolAddress((void**)&wmh, g_wm_h); cudaGetSymbolAddress((void**)&wml, g_wm_l);
    cudaGetSymbolAddress((void**)&w1h, g_w1_h); cudaGetSymbolAddress((void**)&w1l, g_w1_l);
    cudaGetSymbolAddress((void**)&w2h, g_w2_h); cudaGetSymbolAddress((void**)&w2l, g_w2_l);

    static bool init_done = false;
    static cudaStream_t s2, s3, s4;
    static cudaEvent_t evFork, evJoin2, evJoin3, evDone1;
    if (!init_done) {
        cudaFuncSetAttribute(gemm_tc_kernel,
                             cudaFuncAttributeMaxDynamicSharedMemorySize, GEMM_SMEM_BYTES);
        cudaFuncSetAttribute(attn_tc_kernel,
                             cudaFuncAttributeMaxDynamicSharedMemorySize, ATTN_SMEM);
        cudaStreamCreateWithFlags(&s2, cudaStreamNonBlocking);
        cudaStreamCreateWithFlags(&s3, cudaStreamNonBlocking);
        cudaStreamCreateWithFlags(&s4, cudaStreamNonBlocking);
        cudaEventCreateWithFlags(&evFork, cudaEventDisableTiming);
        cudaEventCreateWithFlags(&evJoin2, cudaEventDisableTiming);
        cudaEventCreateWithFlags(&evJoin3, cudaEventDisableTiming);
        cudaEventCreateWithFlags(&evDone1, cudaEventDisableTiming);
        init_done = true;
    }

    dim3 blk(256);

    // ---- fork ----
    cudaEventRecord(evFork, 0);
    cudaStreamWaitEvent(s2, evFork, 0);
    cudaStreamWaitEvent(s3, evFork, 0);
    cudaStreamWaitEvent(s4, evFork, 0);

    // s2: Wm / W1 / W2 transposes (needed at proj GEMM)
    transpose_split_kernel<<<dim3(D_MODEL / 32, D_MODEL / 64), blk, 0, s2>>>(Wm, wmh, wml, D_MODEL, D_MODEL);
    transpose_split_kernel<<<dim3(FF_DIM / 32, D_MODEL / 64), blk, 0, s2>>>(W1, w1h, w1l, D_MODEL, FF_DIM);
    transpose_split_kernel<<<dim3(D_MODEL / 32, FF_DIM / 64), blk, 0, s2>>>(W2, w2h, w2l, FF_DIM, D_MODEL);
    cudaEventRecord(evJoin2, s2);

    // s3: QKV weight transposes + bias concat (needed at QKV GEMMs)
    cudaMemcpyAsync(bqkv,               bq, D_MODEL * sizeof(float), cudaMemcpyDeviceToDevice, s3);
    cudaMemcpyAsync(bqkv + D_MODEL,     bk, D_MODEL * sizeof(float), cudaMemcpyDeviceToDevice, s3);
    cudaMemcpyAsync(bqkv + 2 * D_MODEL, bv, D_MODEL * sizeof(float), cudaMemcpyDeviceToDevice, s3);
    TS3 ts;
    ts.W[0] = Wq; ts.Th[0] = wqkvh;                         ts.Tl[0] = wqkvl;
    ts.W[1] = Wk; ts.Th[1] = wqkvh + D_MODEL * D_MODEL;     ts.Tl[1] = wqkvl + D_MODEL * D_MODEL;
    ts.W[2] = Wv; ts.Th[2] = wqkvh + 2 * D_MODEL * D_MODEL; ts.Tl[2] = wqkvl + 2 * D_MODEL * D_MODEL;
    transpose_split3_kernel<<<dim3(D_MODEL / 32, D_MODEL / 64, 3), blk, 0, s3>>>(ts);
    cudaEventRecord(evJoin3, s3);

    // per-batch grids
    dim3 grid_qkv(3 * D_MODEL / 128, Mh / 128);   // (24, 16)
    dim3 grid_d(D_MODEL / 128, Mh / 128);         // (8, 16)
    dim3 grid_f(FF_DIM / 128,  Mh / 128);         // (32, 16)
    dim3 agrid(L / 128, HEADS);                   // (16, 16)
    const int splitn4 = Mh * D_MODEL / 4;

    // ---- batch pipelines: p=0 on stream 0 (capture), p=1 on s4 ----
    for (int p = 0; p < 2; p++) {
        cudaStream_t st = (p == 0) ? (cudaStream_t)0 : s4;
        const size_t od = (size_t)p * Mh * D_MODEL;   // d-model-sized offset
        const size_t of = (size_t)p * Mh * FF_DIM;    // ff-sized offset

        // split this batch's x
        split_kernel<<<(splitn4 + 255) / 256, blk, 0, st>>>(x + od, xh + od, xl + od, splitn4);

        // QKV weights ready?
        cudaStreamWaitEvent(st, evJoin3, 0);

        gemm_tc_kernel<<<grid_qkv, blk, GEMM_SMEM_BYTES, st>>>(
            xh + od, xl + od, wqkvh, wqkvl, bqkv, nullptr,
            qh + od, ql + od, kh + od, kl + od, vh + od, vl + od,
            Mh, 3 * D_MODEL, D_MODEL, 0);

        attn_tc_kernel<<<agrid, blk, ATTN_SMEM, st>>>(
            qh + od, ql + od, kh + od, kl + od, vh + od, vl + od,
            ah + od, al + od, L);

        // Wm/W1/W2 ready?
        cudaStreamWaitEvent(st, evJoin2, 0);

        gemm_tc_kernel<<<grid_d, blk, GEMM_SMEM_BYTES, st>>>(
            ah + od, al + od, wmh, wml, bm, proj + od,
            nullptr, nullptr, nullptr, nullptr, nullptr, nullptr,
            Mh, D_MODEL, D_MODEL, 0);
        ln_residual_kernel<<<Mh, blk, 0, st>>>(x + od, proj + od, g1, be1,
                                               h + od, hh + od, hl + od);

        gemm_tc_kernel<<<grid_f, blk, GEMM_SMEM_BYTES, st>>>(
            hh + od, hl + od, w1h, w1l, b1, nullptr,
            ffh + of, ffl + of, nullptr, nullptr, nullptr, nullptr,
            Mh, FF_DIM, D_MODEL, 1);
        gemm_tc_kernel<<<grid_d, blk, GEMM_SMEM_BYTES, st>>>(
            ffh + of, ffl + of, w2h, w2l, b2, tmp + od,
            nullptr, nullptr, nullptr, nullptr, nullptr, nullptr,
            Mh, D_MODEL, FF_DIM, 0);
        ln_residual_kernel<<<Mh, blk, 0, st>>>(h + od, tmp + od, g2, be2,
                                               out + od, nullptr, nullptr);
    }

    // join batch-1 pipeline back into the capture stream
    cudaEventRecord(evDone1, s4);
    cudaStreamWaitEvent(0, evDone1, 0);
}